// round 15
// baseline (speedup 1.0000x reference)
#include <cuda_runtime.h>
#include <cuda_bf16.h>
#include <math.h>
#include <stdint.h>

#define BB_   2
#define SS_   2048
#define HID_  1024
#define NH_   16
#define HD_   64
#define FF_   4096
#define TOK_  (BB_*SS_)   // 4096
#define QKVLD 3072

// ---------------- scratch ----------------
__device__ __nv_bfloat16 g_h  [TOK_*HID_];
__device__ __nv_bfloat16 g_qkv[TOK_*3*HID_];       // [TOK, 3072] = q|k|v
__device__ __nv_bfloat16 g_ctx[TOK_*HID_];
__device__ float         g_x2 [TOK_*HID_];
__device__ __nv_bfloat16 g_h2 [TOK_*HID_];
__device__ __nv_bfloat16 g_ff [TOK_*FF_];
__device__ __nv_bfloat16 g_wb [12*1024*1024];      // bf16 weights (q|k|v|o|W1|W2)
__device__ float         g_bqkv[3*HID_];

// ---------------- helpers ----------------
__device__ __forceinline__ uint32_t bf2(float x, float y) {
    __nv_bfloat162 t = __floats2bfloat162_rn(x, y);
    return *reinterpret_cast<uint32_t*>(&t);
}
__device__ __forceinline__ uint32_t smem_u32(const void* p) {
    uint32_t a;
    asm("{ .reg .u64 t; cvta.to.shared.u64 t, %1; cvt.u32.u64 %0, t; }" : "=r"(a) : "l"(p));
    return a;
}
#define CP16(dst, src) \
    asm volatile("cp.async.cg.shared.global [%0], [%1], 16;" :: "r"(dst), "l"(src) : "memory")
#define CP_COMMIT() asm volatile("cp.async.commit_group;" ::: "memory")
#define CP_WAIT1()  asm volatile("cp.async.wait_group 1;" ::: "memory")
#define CP_WAIT0()  asm volatile("cp.async.wait_group 0;" ::: "memory")

#define LDSM4(R0, R1, R2, R3, ADDR) \
    asm volatile("ldmatrix.sync.aligned.m8n8.x4.shared.b16 {%0,%1,%2,%3}, [%4];" \
        : "=r"(R0), "=r"(R1), "=r"(R2), "=r"(R3) : "r"(ADDR))
#define LDSM4T(R0, R1, R2, R3, ADDR) \
    asm volatile("ldmatrix.sync.aligned.m8n8.x4.trans.shared.b16 {%0,%1,%2,%3}, [%4];" \
        : "=r"(R0), "=r"(R1), "=r"(R2), "=r"(R3) : "r"(ADDR))

__device__ __forceinline__ void mma16816(float* c, const uint32_t* a, uint32_t b0, uint32_t b1) {
    asm volatile(
        "mma.sync.aligned.m16n8k16.row.col.f32.bf16.bf16.f32 "
        "{%0,%1,%2,%3}, {%4,%5,%6,%7}, {%8,%9}, {%0,%1,%2,%3};"
        : "+f"(c[0]), "+f"(c[1]), "+f"(c[2]), "+f"(c[3])
        : "r"(a[0]), "r"(a[1]), "r"(a[2]), "r"(a[3]), "r"(b0), "r"(b1));
}

// ---------------- fused conversion: weights -> bf16 + bias pack ----------------
__global__ void convert_all_kernel(
    const float* __restrict__ Wq, const float* __restrict__ Wk,
    const float* __restrict__ Wv, const float* __restrict__ Wo,
    const float* __restrict__ W1, const float* __restrict__ W2,
    const float* __restrict__ bq, const float* __restrict__ bk,
    const float* __restrict__ bv,
    __nv_bfloat16* __restrict__ wb, float* __restrict__ bqkv)
{
    int bid = blockIdx.x;
    if (bid < 4096) {
        int i = bid * 256 + threadIdx.x;
        int seg = i >> 18, off = i & 262143;
        const float4* sp;
        __nv_bfloat16* dp;
        if      (seg == 0) { sp = (const float4*)Wq; dp = wb; }
        else if (seg == 1) { sp = (const float4*)Wk; dp = wb + 1024*1024; }
        else if (seg == 2) { sp = (const float4*)Wv; dp = wb + 2*1024*1024; }
        else               { sp = (const float4*)Wo; dp = wb + 3*1024*1024; }
        float4 v = sp[off];
        reinterpret_cast<uint2*>(dp)[off] = make_uint2(bf2(v.x, v.y), bf2(v.z, v.w));
    } else if (bid < 12288) {
        int i = (bid - 4096) * 256 + threadIdx.x;
        int seg = i >> 20, off = i & 1048575;
        const float4* sp = seg ? (const float4*)W2 : (const float4*)W1;
        __nv_bfloat16* dp = seg ? (wb + 8*1024*1024) : (wb + 4*1024*1024);
        float4 v = sp[off];
        reinterpret_cast<uint2*>(dp)[off] = make_uint2(bf2(v.x, v.y), bf2(v.z, v.w));
    } else {
        int i = (bid - 12288) * 256 + threadIdx.x;
        if (i < HID_)            bqkv[i] = bq[i];
        else if (i < 2 * HID_)   bqkv[i] = bk[i - HID_];
        else if (i < 3 * HID_)   bqkv[i] = bv[i - 2 * HID_];
    }
}

// ---------------- block reduction ----------------
template<bool MAX>
__device__ __forceinline__ float block_reduce_256(float v) {
    __shared__ float sh[8];
    int lane = threadIdx.x & 31, w = threadIdx.x >> 5;
    #pragma unroll
    for (int o = 16; o; o >>= 1) {
        float u = __shfl_xor_sync(0xffffffffu, v, o);
        v = MAX ? fmaxf(v, u) : v + u;
    }
    if (lane == 0) sh[w] = v;
    __syncthreads();
    if (w == 0) {
        v = sh[lane & 7];
        #pragma unroll
        for (int o = 4; o; o >>= 1) {
            float u = __shfl_xor_sync(0xffffffffu, v, o);
            v = MAX ? fmaxf(v, u) : v + u;
        }
        if (lane == 0) sh[0] = v;
    }
    __syncthreads();
    float r = sh[0];
    __syncthreads();
    return r;
}

// ---------------- LayerNorm (fp32 in -> bf16 out) ----------------
__global__ void ln_kernel(const float* __restrict__ x, const float* __restrict__ g,
                          const float* __restrict__ beta, __nv_bfloat16* __restrict__ out) {
    size_t base = (size_t)blockIdx.x * HID_;
    const float4* xp = reinterpret_cast<const float4*>(x + base);
    int t = threadIdx.x;
    float4 v = xp[t];
    float s = v.x + v.y + v.z + v.w;
    s = block_reduce_256<false>(s);
    float mean = s * (1.0f / HID_);
    float dx = v.x - mean, dy = v.y - mean, dz = v.z - mean, dw = v.w - mean;
    float q = dx*dx + dy*dy + dz*dz + dw*dw;
    q = block_reduce_256<false>(q);
    float r = rsqrtf(q * (1.0f / HID_) + 1e-5f);
    float4 gv = reinterpret_cast<const float4*>(g)[t];
    float4 bv = reinterpret_cast<const float4*>(beta)[t];
    uint2 o;
    o.x = bf2(dx * r * gv.x + bv.x, dy * r * gv.y + bv.y);
    o.y = bf2(dz * r * gv.z + bv.z, dw * r * gv.w + bv.w);
    reinterpret_cast<uint2*>(out + base)[t] = o;
}

// ---------------- flash attention: register P, warps 4(M) x 2(keys) ----------------
// Warp = 32 rows x 32-key half. K/V LDSM redundancy 4x (was 8x). Q reloaded per kk
// (reg budget). ctx + row-sum halves merged once at the end via smem.
#define FFS 72
#define FQ  0
#define FK  (128*FFS)
#define FV  (FK + 3*64*FFS)
#define FL_FLT ((FV + 3*64*FFS) * 2)
#define FL_SMEM (FL_FLT + 2048 * 4)

__global__ __launch_bounds__(256, 2) void flash_kernel(
    const __nv_bfloat16* __restrict__ qkv,
    const float* __restrict__ am, __nv_bfloat16* __restrict__ ctx)
{
    extern __shared__ __align__(16) char smc[];
    float* Madd = reinterpret_cast<float*>(smc + FL_FLT);
    // end-of-kernel merge buffers overlay the K/V region (55.3KB >= 32KB + 512B)
    float* mbuf    = reinterpret_cast<float*>(smc + FK * 2);        // [4][32][64]
    float* lsumbuf = mbuf + 4 * 32 * 64;                            // [128]

    const int tid = threadIdx.x, lane = tid & 31, wid = tid >> 5;
    const int wm = wid >> 1, wn = wid & 1;
    const int gr = lane >> 2, c2 = (lane & 3) << 1;
    const int qq = lane >> 3, l8 = lane & 7;
    const int arow = ((qq & 1) << 3) + l8, acol = (qq >> 1) << 3;
    const int brow = ((qq >> 1) << 3) + l8, bcol = (qq & 1) << 3;
    const int tkrow = ((qq & 1) << 3) + l8, tncol = (qq >> 1) << 3;
    const int qt = blockIdx.x, bh = blockIdx.y;
    const int bb = bh >> 4, hh = bh & 15;
    const int q0 = qt * 128;
    const int mrow0 = wm * 32;          // warp's 32-row block
    const int kh0 = wn * 32;            // warp's 32-key half within tile

    const __nv_bfloat16* Qg = qkv + ((size_t)bb * SS_ + q0) * QKVLD + hh * 64;
    const __nv_bfloat16* Kg = qkv + (size_t)bb * SS_ * QKVLD + HID_ + hh * 64;
    const __nv_bfloat16* Vg = qkv + (size_t)bb * SS_ * QKVLD + 2 * HID_ + hh * 64;

    const uint32_t sb = smem_u32(smc);
    const uint32_t sQ = sb + FQ * 2;

    // stage Q (128x64) — own group
    #pragma unroll
    for (int u = 0; u < 4; u++) {
        int idx = tid + u * 256;
        int r = idx >> 3, c8 = (idx & 7) << 3;
        CP16(sQ + (uint32_t)((r * FFS + c8) * 2), Qg + (size_t)r * QKVLD + c8);
    }
    CP_COMMIT();
    #pragma unroll
    for (int u = 0; u < 8; u++) {
        int i = tid + u * 256;
        Madd[i] = (__ldg(&am[(size_t)bb * SS_ + i]) - 1.0f) * 10000.0f;
    }

    auto load_kv = [&](int j, int s) {
        const int j0 = j * 64;
        uint32_t kb = sb + (uint32_t)((FK + s * 64 * FFS) * 2);
        uint32_t vb = sb + (uint32_t)((FV + s * 64 * FFS) * 2);
        #pragma unroll
        for (int u = 0; u < 2; u++) {
            int idx = tid + u * 256;
            int r = idx >> 3, c8 = (idx & 7) << 3;
            CP16(kb + (uint32_t)((r * FFS + c8) * 2), Kg + (size_t)(j0 + r) * QKVLD + c8);
        }
        #pragma unroll
        for (int u = 0; u < 2; u++) {
            int idx = tid + u * 256;
            int r = idx >> 3, c8 = (idx & 7) << 3;
            CP16(vb + (uint32_t)((r * FFS + c8) * 2), Vg + (size_t)(j0 + r) * QKVLD + c8);
        }
        CP_COMMIT();
    };
    load_kv(0, 0);
    load_kv(1, 1);

    float ctxa[2][8][4] = {};       // 32 rows x 64 dh
    float lrow[2][2] = {};          // partial row sums (this key half)

    const int IT = SS_ / 64;   // 32
    int s = 0;
    for (int j = 0; j < IT; j++) {
        if (j == IT - 1) { CP_WAIT0(); } else { CP_WAIT1(); }
        __syncthreads();
        int ns = s + 2; if (ns >= 3) ns -= 3;
        if (j + 2 < IT) load_kv(j + 2, ns);

        // ---- S = Q @ K^T : 32 rows x 32 keys (k = dh 64) ----
        float sacc[2][4][4] = {};
        const uint32_t sKs = sb + (uint32_t)((FK + s * 64 * FFS) * 2);
        #pragma unroll
        for (int kk = 0; kk < 4; kk++) {
            uint32_t qf2[2][4];
            #pragma unroll
            for (int mt = 0; mt < 2; mt++) {
                int rr = mrow0 + mt * 16 + arow;
                LDSM4(qf2[mt][0], qf2[mt][1], qf2[mt][2], qf2[mt][3],
                      sQ + (uint32_t)((rr * FFS + kk * 16 + acol) * 2));
            }
            uint32_t kb4[4][2];
            #pragma unroll
            for (int t16 = 0; t16 < 2; t16++) {
                int nn = kh0 + t16 * 16 + brow;
                LDSM4(kb4[2*t16][0], kb4[2*t16][1], kb4[2*t16+1][0], kb4[2*t16+1][1],
                      sKs + (uint32_t)((nn * FFS + kk * 16 + bcol) * 2));
            }
            #pragma unroll
            for (int mt = 0; mt < 2; mt++)
                #pragma unroll
                for (int nt = 0; nt < 4; nt++)
                    mma16816(sacc[mt][nt], qf2[mt], kb4[nt][0], kb4[nt][1]);
        }

        // ---- P = exp(s*0.125 + madd) -> register A-frags; partial row sums ----
        const int j0 = j * 64;
        uint32_t pa[2][2][4];
        #pragma unroll
        for (int mt = 0; mt < 2; mt++) {
            float ls0 = 0.f, ls1 = 0.f;
            #pragma unroll
            for (int nt = 0; nt < 4; nt++) {
                float2 md = *reinterpret_cast<const float2*>(&Madd[j0 + kh0 + nt * 8 + c2]);
                float p0 = __expf(fmaf(sacc[mt][nt][0], 0.125f, md.x));
                float p1 = __expf(fmaf(sacc[mt][nt][1], 0.125f, md.y));
                float p2 = __expf(fmaf(sacc[mt][nt][2], 0.125f, md.x));
                float p3 = __expf(fmaf(sacc[mt][nt][3], 0.125f, md.y));
                ls0 += p0 + p1;
                ls1 += p2 + p3;
                int kt = nt >> 1;
                if ((nt & 1) == 0) { pa[mt][kt][0] = bf2(p0, p1); pa[mt][kt][1] = bf2(p2, p3); }
                else               { pa[mt][kt][2] = bf2(p0, p1); pa[mt][kt][3] = bf2(p2, p3); }
            }
            ls0 += __shfl_xor_sync(0xffffffffu, ls0, 1);
            ls0 += __shfl_xor_sync(0xffffffffu, ls0, 2);
            ls1 += __shfl_xor_sync(0xffffffffu, ls1, 1);
            ls1 += __shfl_xor_sync(0xffffffffu, ls1, 2);
            lrow[mt][0] += ls0;
            lrow[mt][1] += ls1;
        }

        // ---- ctx += P @ V : 32 rows x 64 dh (k = 32 keys) ----
        const uint32_t sVs = sb + (uint32_t)((FV + s * 64 * FFS) * 2);
        #pragma unroll
        for (int kt = 0; kt < 2; kt++) {
            uint32_t vb4[8][2];
            #pragma unroll
            for (int t4 = 0; t4 < 4; t4++) {
                int kr = kh0 + kt * 16 + tkrow;
                int nc = t4 * 16 + tncol;
                LDSM4T(vb4[2*t4][0], vb4[2*t4][1], vb4[2*t4+1][0], vb4[2*t4+1][1],
                       sVs + (uint32_t)((kr * FFS + nc) * 2));
            }
            #pragma unroll
            for (int mt = 0; mt < 2; mt++)
                #pragma unroll
                for (int nt = 0; nt < 8; nt++)
                    mma16816(ctxa[mt][nt], pa[mt][kt], vb4[nt][0], vb4[nt][1]);
        }
        s++; if (s == 3) s = 0;
    }

    // ---- merge key-halves: wn=1 stores, wn=0 adds + writes out ----
    __syncthreads();                       // all KV reads done; safe to overlay
    if (wn == 1) {
        #pragma unroll
        for (int mt = 0; mt < 2; mt++) {
            #pragma unroll
            for (int nt = 0; nt < 8; nt++) {
                int rl = mt * 16 + gr;
                float* dst = mbuf + (wm * 32 + rl) * 64 + nt * 8 + c2;
                dst[0] = ctxa[mt][nt][0]; dst[1] = ctxa[mt][nt][1];
                dst += 8 * 64;
                dst[0] = ctxa[mt][nt][2]; dst[1] = ctxa[mt][nt][3];
            }
            if ((lane & 3) == 0) {
                lsumbuf[wm * 32 + mt * 16 + gr]     = lrow[mt][0];
                lsumbuf[wm * 32 + mt * 16 + 8 + gr] = lrow[mt][1];
            }
        }
    }
    __syncthreads();
    if (wn == 0) {
        #pragma unroll
        for (int mt = 0; mt < 2; mt++) {
            int rl = mt * 16 + gr;
            float inv0 = 1.0f / (lrow[mt][0] + lsumbuf[wm * 32 + rl]);
            float inv1 = 1.0f / (lrow[mt][1] + lsumbuf[wm * 32 + rl + 8]);
            size_t r0g = ((size_t)bb * SS_ + q0 + mrow0 + rl) * HID_ + hh * 64;
            size_t r1g = r0g + 8 * HID_;
            #pragma unroll
            for (int nt = 0; nt < 8; nt++) {
                const float* src = mbuf + (wm * 32 + rl) * 64 + nt * 8 + c2;
                float v0 = (ctxa[mt][nt][0] + src[0]) * inv0;
                float v1 = (ctxa[mt][nt][1] + src[1]) * inv0;
                float v2 = (ctxa[mt][nt][2] + src[8 * 64]) * inv1;
                float v3 = (ctxa[mt][nt][3] + src[8 * 64 + 1]) * inv1;
                *reinterpret_cast<uint32_t*>(ctx + r0g + nt * 8 + c2) = bf2(v0, v1);
                *reinterpret_cast<uint32_t*>(ctx + r1g + nt * 8 + c2) = bf2(v2, v3);
            }
        }
    }
}

// ---------------- bf16 mma GEMM (R10 proven config) ----------------
// EPI: 0 = +bias -> bf16; 2 = gelu(+bias) -> bf16; 3 = +bias+residual -> fp32
template<int EPI>
__global__ __launch_bounds__(256, 2) void tc_gemm(
    int M, int N, int K,
    const __nv_bfloat16* __restrict__ A,  int lda,
    const __nv_bfloat16* __restrict__ Bm, int ldb,
    float* __restrict__ Cf, __nv_bfloat16* __restrict__ Cb, int ldc,
    const float* __restrict__ bias, const float* __restrict__ residual)
{
    constexpr int RS  = 72;
    constexpr int ASZ = 128 * RS;
    constexpr int STG = 2 * ASZ;
    constexpr int NT  = 4;

    extern __shared__ __align__(16) char smc[];

    const int tid  = threadIdx.x;
    const int wid  = tid >> 5, lane = tid & 31;
    const int wm   = wid >> 2, wn = wid & 3;
    const int qq   = lane >> 3, l8 = lane & 7;
    const int arow = ((qq & 1) << 3) + l8, acol = (qq >> 1) << 3;
    const int brow = ((qq >> 1) << 3) + l8, bcol = (qq & 1) << 3;
    const int row0 = blockIdx.y * 128;
    const int col0 = blockIdx.x * 128;

    const uint32_t sbase = smem_u32(smc);

    float acc[4][NT][4];
    #pragma unroll
    for (int i = 0; i < 4; i++)
        #pragma unroll
        for (int j = 0; j < NT; j++)
            #pragma unroll
            for (int e = 0; e < 4; e++) acc[i][j][e] = 0.0f;

    const int nk = K >> 6;

    auto load_stage = [&](int i, int s) {
        const int k0 = i << 6;
        uint32_t abase = sbase + (uint32_t)(s * STG) * 2u;
        uint32_t bbase = abase + (uint32_t)ASZ * 2u;
        #pragma unroll
        for (int u = 0; u < 4; u++) {
            int idx = tid + u * 256;
            int r = idx >> 3, c8 = (idx & 7) << 3;
            CP16(abase + (uint32_t)(r * RS + c8) * 2u,
                 A + (size_t)(row0 + r) * lda + k0 + c8);
        }
        #pragma unroll
        for (int u = 0; u < 4; u++) {
            int idx = tid + u * 256;
            int r = idx >> 3, c8 = (idx & 7) << 3;
            CP16(bbase + (uint32_t)(r * RS + c8) * 2u,
                 Bm + (size_t)(col0 + r) * ldb + k0 + c8);
        }
        CP_COMMIT();
    };

    load_stage(0, 0);
    load_stage(1, 1);

    int s = 0;
    for (int i = 0; i < nk; i++) {
        if (i == nk - 1) { CP_WAIT0(); } else { CP_WAIT1(); }
        __syncthreads();
        int ns = s + 2; if (ns >= 3) ns -= 3;
        if (i + 2 < nk) load_stage(i + 2, ns);

        const uint32_t sAs = sbase + (uint32_t)(s * STG) * 2u;
        const uint32_t sBs = sAs + (uint32_t)ASZ * 2u;

        #pragma unroll
        for (int kk = 0; kk < 4; kk++) {
            uint32_t af[4][4];
            #pragma unroll
            for (int mt = 0; mt < 4; mt++) {
                int rr = wm * 64 + mt * 16 + arow;
                LDSM4(af[mt][0], af[mt][1], af[mt][2], af[mt][3],
                      sAs + (uint32_t)((rr * RS + kk * 16 + acol) * 2));
            }
            uint32_t bf[NT][2];
            #pragma unroll
            for (int ntp = 0; ntp < NT / 2; ntp++) {
                int nn = wn * 32 + ntp * 16 + brow;
                LDSM4(bf[2*ntp][0], bf[2*ntp][1], bf[2*ntp+1][0], bf[2*ntp+1][1],
                      sBs + (uint32_t)((nn * RS + kk * 16 + bcol) * 2));
            }
            #pragma unroll
            for (int nt = 0; nt < NT; nt++)
                #pragma unroll
                for (int mt = 0; mt < 4; mt++)
                    mma16816(acc[mt][nt], af[mt], bf[nt][0], bf[nt][1]);
        }
        s++; if (s == 3) s = 0;
    }

    #pragma unroll
    for (int mt = 0; mt < 4; mt++) {
        #pragma unroll
        for (int nt = 0; nt < NT; nt++) {
            int r0 = row0 + wm * 64 + mt * 16 + (lane >> 2);
            int c0 = col0 + wn * 32 + nt * 8 + 2 * (lane & 3);
            #pragma unroll
            for (int half = 0; half < 2; half++) {
                int r = r0 + half * 8;
                float v0 = acc[mt][nt][2 * half + 0];
                float v1 = acc[mt][nt][2 * half + 1];
                v0 += __ldg(&bias[c0]);
                v1 += __ldg(&bias[c0 + 1]);
                if (EPI == 2) {
                    v0 = 0.5f * v0 * (1.0f + erff(v0 * 0.70710678118654752f));
                    v1 = 0.5f * v1 * (1.0f + erff(v1 * 0.70710678118654752f));
                }
                if (EPI == 3) {
                    float2 rr = *reinterpret_cast<const float2*>(
                        residual + (size_t)r * ldc + c0);
                    v0 += rr.x; v1 += rr.y;
                    float2 o; o.x = v0; o.y = v1;
                    *reinterpret_cast<float2*>(Cf + (size_t)r * ldc + c0) = o;
                } else {
                    *reinterpret_cast<uint32_t*>(Cb + (size_t)r * ldc + c0) = bf2(v0, v1);
                }
            }
        }
    }
}

// ---------------- launch ----------------
extern "C" void kernel_launch(void* const* d_in, const int* in_sizes, int n_in,
                              void* d_out, int out_size) {
    const float* x   = (const float*)d_in[0];
    const float* am  = (const float*)d_in[1];
    const float* Wq  = (const float*)d_in[2];
    const float* bq  = (const float*)d_in[3];
    const float* Wk  = (const float*)d_in[4];
    const float* bk  = (const float*)d_in[5];
    const float* Wv  = (const float*)d_in[6];
    const float* bv  = (const float*)d_in[7];
    const float* Wo  = (const float*)d_in[8];
    const float* bo  = (const float*)d_in[9];
    const float* W1  = (const float*)d_in[10];
    const float* b1  = (const float*)d_in[11];
    const float* W2  = (const float*)d_in[12];
    const float* b2  = (const float*)d_in[13];
    const float* g1  = (const float*)d_in[14];
    const float* be1 = (const float*)d_in[15];
    const float* g2  = (const float*)d_in[16];
    const float* be2 = (const float*)d_in[17];
    float* out = (float*)d_out;

    __nv_bfloat16 *h, *qkv, *ctx, *h2, *ff, *wb;
    float *x2, *bqkv;
    cudaGetSymbolAddress((void**)&h,    g_h);
    cudaGetSymbolAddress((void**)&qkv,  g_qkv);
    cudaGetSymbolAddress((void**)&ctx,  g_ctx);
    cudaGetSymbolAddress((void**)&x2,   g_x2);
    cudaGetSymbolAddress((void**)&h2,   g_h2);
    cudaGetSymbolAddress((void**)&ff,   g_ff);
    cudaGetSymbolAddress((void**)&wb,   g_wb);
    cudaGetSymbolAddress((void**)&bqkv, g_bqkv);

    __nv_bfloat16* rWqkv = wb;
    __nv_bfloat16* rWo = wb + 3 * 1024 * 1024;
    __nv_bfloat16* rW1 = wb + 4 * 1024 * 1024;
    __nv_bfloat16* rW2 = wb + 8 * 1024 * 1024;

    const int SM3 = 3 * 2 * 128 * 72 * 2;            // 110592 bytes
    cudaFuncSetAttribute(tc_gemm<0>, cudaFuncAttributeMaxDynamicSharedMemorySize, SM3);
    cudaFuncSetAttribute(tc_gemm<2>, cudaFuncAttributeMaxDynamicSharedMemorySize, SM3);
    cudaFuncSetAttribute(tc_gemm<3>, cudaFuncAttributeMaxDynamicSharedMemorySize, SM3);
    cudaFuncSetAttribute(flash_kernel, cudaFuncAttributeMaxDynamicSharedMemorySize, FL_SMEM);

    dim3 blk(256);

    convert_all_kernel<<<12300, blk>>>(Wq, Wk, Wv, Wo, W1, W2, bq, bk, bv, wb, bqkv);
    ln_kernel<<<TOK_, blk>>>(x, g1, be1, h);
    tc_gemm<0><<<dim3(QKVLD/128, TOK_/128), blk, SM3>>>(TOK_, QKVLD, HID_,
        h, HID_,  rWqkv, HID_,  nullptr, qkv, QKVLD,  bqkv, nullptr);
    flash_kernel<<<dim3(SS_/128, BB_*NH_), blk, FL_SMEM>>>(qkv, am, ctx);
    tc_gemm<3><<<dim3(HID_/128, TOK_/128), blk, SM3>>>(TOK_, HID_, HID_,
        ctx, HID_,  rWo, HID_,  x2, nullptr, HID_,  bo, x);
    ln_kernel<<<TOK_, blk>>>(x2, g2, be2, h2);
    tc_gemm<2><<<dim3(FF_/128, TOK_/128), blk, SM3>>>(TOK_, FF_, HID_,
        h2, HID_,  rW1, HID_,  nullptr, ff, FF_,  b1, nullptr);
    tc_gemm<3><<<dim3(HID_/128, TOK_/128), blk, SM3>>>(TOK_, HID_, FF_,
        ff, FF_,  rW2, FF_,  out, nullptr, HID_,  b2, x2);
}

// round 16
// speedup vs baseline: 1.0291x; 1.0291x over previous
#include <cuda_runtime.h>
#include <cuda_bf16.h>
#include <math.h>
#include <stdint.h>

#define BB_   2
#define SS_   2048
#define HID_  1024
#define NH_   16
#define HD_   64
#define FF_   4096
#define TOK_  (BB_*SS_)   // 4096
#define QKVLD 3072
#define LOG2E 1.4426950408889634f

// ---------------- scratch ----------------
__device__ __nv_bfloat16 g_h  [TOK_*HID_];
__device__ __nv_bfloat16 g_qkv[TOK_*3*HID_];       // [TOK, 3072] = q|k|v
__device__ __nv_bfloat16 g_ctx[TOK_*HID_];
__device__ float         g_x2 [TOK_*HID_];
__device__ __nv_bfloat16 g_h2 [TOK_*HID_];
__device__ __nv_bfloat16 g_ff [TOK_*FF_];
__device__ __nv_bfloat16 g_wb [12*1024*1024];      // bf16 weights (q|k|v|o|W1|W2)
__device__ float         g_bqkv[3*HID_];

// ---------------- helpers ----------------
__device__ __forceinline__ uint32_t bf2(float x, float y) {
    __nv_bfloat162 t = __floats2bfloat162_rn(x, y);
    return *reinterpret_cast<uint32_t*>(&t);
}
__device__ __forceinline__ float ex2(float x) {
    float y;
    asm("ex2.approx.f32 %0, %1;" : "=f"(y) : "f"(x));
    return y;
}
__device__ __forceinline__ uint32_t smem_u32(const void* p) {
    uint32_t a;
    asm("{ .reg .u64 t; cvta.to.shared.u64 t, %1; cvt.u32.u64 %0, t; }" : "=r"(a) : "l"(p));
    return a;
}
#define CP16(dst, src) \
    asm volatile("cp.async.cg.shared.global [%0], [%1], 16;" :: "r"(dst), "l"(src) : "memory")
#define CP_COMMIT() asm volatile("cp.async.commit_group;" ::: "memory")
#define CP_WAIT2()  asm volatile("cp.async.wait_group 2;" ::: "memory")
#define CP_WAIT1()  asm volatile("cp.async.wait_group 1;" ::: "memory")
#define CP_WAIT0()  asm volatile("cp.async.wait_group 0;" ::: "memory")

#define LDSM4(R0, R1, R2, R3, ADDR) \
    asm volatile("ldmatrix.sync.aligned.m8n8.x4.shared.b16 {%0,%1,%2,%3}, [%4];" \
        : "=r"(R0), "=r"(R1), "=r"(R2), "=r"(R3) : "r"(ADDR))
#define LDSM4T(R0, R1, R2, R3, ADDR) \
    asm volatile("ldmatrix.sync.aligned.m8n8.x4.trans.shared.b16 {%0,%1,%2,%3}, [%4];" \
        : "=r"(R0), "=r"(R1), "=r"(R2), "=r"(R3) : "r"(ADDR))

__device__ __forceinline__ void mma16816(float* c, const uint32_t* a, uint32_t b0, uint32_t b1) {
    asm volatile(
        "mma.sync.aligned.m16n8k16.row.col.f32.bf16.bf16.f32 "
        "{%0,%1,%2,%3}, {%4,%5,%6,%7}, {%8,%9}, {%0,%1,%2,%3};"
        : "+f"(c[0]), "+f"(c[1]), "+f"(c[2]), "+f"(c[3])
        : "r"(a[0]), "r"(a[1]), "r"(a[2]), "r"(a[3]), "r"(b0), "r"(b1));
}

// ---------------- fused conversion: weights -> bf16 + bias pack ----------------
__global__ void convert_all_kernel(
    const float* __restrict__ Wq, const float* __restrict__ Wk,
    const float* __restrict__ Wv, const float* __restrict__ Wo,
    const float* __restrict__ W1, const float* __restrict__ W2,
    const float* __restrict__ bq, const float* __restrict__ bk,
    const float* __restrict__ bv,
    __nv_bfloat16* __restrict__ wb, float* __restrict__ bqkv)
{
    int bid = blockIdx.x;
    if (bid < 4096) {
        int i = bid * 256 + threadIdx.x;
        int seg = i >> 18, off = i & 262143;
        const float4* sp;
        __nv_bfloat16* dp;
        if      (seg == 0) { sp = (const float4*)Wq; dp = wb; }
        else if (seg == 1) { sp = (const float4*)Wk; dp = wb + 1024*1024; }
        else if (seg == 2) { sp = (const float4*)Wv; dp = wb + 2*1024*1024; }
        else               { sp = (const float4*)Wo; dp = wb + 3*1024*1024; }
        float4 v = sp[off];
        reinterpret_cast<uint2*>(dp)[off] = make_uint2(bf2(v.x, v.y), bf2(v.z, v.w));
    } else if (bid < 12288) {
        int i = (bid - 4096) * 256 + threadIdx.x;
        int seg = i >> 20, off = i & 1048575;
        const float4* sp = seg ? (const float4*)W2 : (const float4*)W1;
        __nv_bfloat16* dp = seg ? (wb + 8*1024*1024) : (wb + 4*1024*1024);
        float4 v = sp[off];
        reinterpret_cast<uint2*>(dp)[off] = make_uint2(bf2(v.x, v.y), bf2(v.z, v.w));
    } else {
        int i = (bid - 12288) * 256 + threadIdx.x;
        if (i < HID_)            bqkv[i] = bq[i];
        else if (i < 2 * HID_)   bqkv[i] = bk[i - HID_];
        else if (i < 3 * HID_)   bqkv[i] = bv[i - 2 * HID_];
    }
}

// ---------------- block reduction ----------------
template<bool MAX>
__device__ __forceinline__ float block_reduce_256(float v) {
    __shared__ float sh[8];
    int lane = threadIdx.x & 31, w = threadIdx.x >> 5;
    #pragma unroll
    for (int o = 16; o; o >>= 1) {
        float u = __shfl_xor_sync(0xffffffffu, v, o);
        v = MAX ? fmaxf(v, u) : v + u;
    }
    if (lane == 0) sh[w] = v;
    __syncthreads();
    if (w == 0) {
        v = sh[lane & 7];
        #pragma unroll
        for (int o = 4; o; o >>= 1) {
            float u = __shfl_xor_sync(0xffffffffu, v, o);
            v = MAX ? fmaxf(v, u) : v + u;
        }
        if (lane == 0) sh[0] = v;
    }
    __syncthreads();
    float r = sh[0];
    __syncthreads();
    return r;
}

// ---------------- LayerNorm (fp32 in -> bf16 out) ----------------
__global__ void ln_kernel(const float* __restrict__ x, const float* __restrict__ g,
                          const float* __restrict__ beta, __nv_bfloat16* __restrict__ out) {
    size_t base = (size_t)blockIdx.x * HID_;
    const float4* xp = reinterpret_cast<const float4*>(x + base);
    int t = threadIdx.x;
    float4 v = xp[t];
    float s = v.x + v.y + v.z + v.w;
    s = block_reduce_256<false>(s);
    float mean = s * (1.0f / HID_);
    float dx = v.x - mean, dy = v.y - mean, dz = v.z - mean, dw = v.w - mean;
    float q = dx*dx + dy*dy + dz*dz + dw*dw;
    q = block_reduce_256<false>(q);
    float r = rsqrtf(q * (1.0f / HID_) + 1e-5f);
    float4 gv = reinterpret_cast<const float4*>(g)[t];
    float4 bv = reinterpret_cast<const float4*>(beta)[t];
    uint2 o;
    o.x = bf2(dx * r * gv.x + bv.x, dy * r * gv.y + bv.y);
    o.y = bf2(dz * r * gv.z + bv.z, dw * r * gv.w + bv.w);
    reinterpret_cast<uint2*>(out + base)[t] = o;
}

// ---------------- flash attention: R14 layout (register P, M-partitioned warps,
// 3-stage KV ring, 1 barrier/iter) + exp2-folded softmax ----------------
#define FFS 72
#define FQ  0
#define FK  (128*FFS)
#define FV  (FK + 3*64*FFS)
#define FL_FLT ((FV + 3*64*FFS) * 2)
#define FL_SMEM (FL_FLT + 2048 * 4)
#define SC2 (0.125f * LOG2E)

__global__ __launch_bounds__(256, 2) void flash_kernel(
    const __nv_bfloat16* __restrict__ qkv,
    const float* __restrict__ am, __nv_bfloat16* __restrict__ ctx)
{
    extern __shared__ __align__(16) char smc[];
    float* Madd = reinterpret_cast<float*>(smc + FL_FLT);

    const int tid = threadIdx.x, lane = tid & 31, wid = tid >> 5;   // wid 0..7
    const int gr = lane >> 2, c2 = (lane & 3) << 1;
    const int qq = lane >> 3, l8 = lane & 7;
    const int arow = ((qq & 1) << 3) + l8, acol = (qq >> 1) << 3;
    const int brow = ((qq >> 1) << 3) + l8, bcol = (qq & 1) << 3;
    const int tkrow = ((qq & 1) << 3) + l8, tncol = (qq >> 1) << 3;
    const int qt = blockIdx.x, bh = blockIdx.y;
    const int bb = bh >> 4, hh = bh & 15;
    const int q0 = qt * 128;
    const int mrow0 = wid * 16;

    const __nv_bfloat16* Qg = qkv + ((size_t)bb * SS_ + q0) * QKVLD + hh * 64;
    const __nv_bfloat16* Kg = qkv + (size_t)bb * SS_ * QKVLD + HID_ + hh * 64;
    const __nv_bfloat16* Vg = qkv + (size_t)bb * SS_ * QKVLD + 2 * HID_ + hh * 64;

    const uint32_t sb = smem_u32(smc);
    const uint32_t sQ = sb + FQ * 2;

    // stage Q (128x64) — own group
    #pragma unroll
    for (int u = 0; u < 4; u++) {
        int idx = tid + u * 256;
        int r = idx >> 3, c8 = (idx & 7) << 3;
        CP16(sQ + (uint32_t)((r * FFS + c8) * 2), Qg + (size_t)r * QKVLD + c8);
    }
    CP_COMMIT();
    // mask-add, pre-scaled by log2e (feeds ex2 directly)
    #pragma unroll
    for (int u = 0; u < 8; u++) {
        int i = tid + u * 256;
        Madd[i] = (__ldg(&am[(size_t)bb * SS_ + i]) - 1.0f) * (10000.0f * LOG2E);
    }

    auto load_kv = [&](int j, int s) {
        const int j0 = j * 64;
        uint32_t kb = sb + (uint32_t)((FK + s * 64 * FFS) * 2);
        uint32_t vb = sb + (uint32_t)((FV + s * 64 * FFS) * 2);
        #pragma unroll
        for (int u = 0; u < 2; u++) {
            int idx = tid + u * 256;
            int r = idx >> 3, c8 = (idx & 7) << 3;
            CP16(kb + (uint32_t)((r * FFS + c8) * 2), Kg + (size_t)(j0 + r) * QKVLD + c8);
        }
        #pragma unroll
        for (int u = 0; u < 2; u++) {
            int idx = tid + u * 256;
            int r = idx >> 3, c8 = (idx & 7) << 3;
            CP16(vb + (uint32_t)((r * FFS + c8) * 2), Vg + (size_t)(j0 + r) * QKVLD + c8);
        }
        CP_COMMIT();
    };
    load_kv(0, 0);
    load_kv(1, 1);

    // hoist Q fragments
    CP_WAIT2();
    __syncthreads();
    uint32_t qf[4][4];
    #pragma unroll
    for (int kk = 0; kk < 4; kk++) {
        int rr = mrow0 + arow;
        LDSM4(qf[kk][0], qf[kk][1], qf[kk][2], qf[kk][3],
              sQ + (uint32_t)((rr * FFS + kk * 16 + acol) * 2));
    }

    float ctxa[8][4] = {};
    float lrow0 = 0.f, lrow1 = 0.f;

    const int IT = SS_ / 64;   // 32
    int s = 0;
    for (int j = 0; j < IT; j++) {
        if (j == IT - 1) { CP_WAIT0(); } else { CP_WAIT1(); }
        __syncthreads();
        int ns = s + 2; if (ns >= 3) ns -= 3;
        if (j + 2 < IT) load_kv(j + 2, ns);

        // ---- S = Q @ K^T : 16 rows x 64 keys ----
        float sacc[8][4] = {};
        const uint32_t sKs = sb + (uint32_t)((FK + s * 64 * FFS) * 2);
        #pragma unroll
        for (int kk = 0; kk < 4; kk++) {
            uint32_t kb4[8][2];
            #pragma unroll
            for (int t4 = 0; t4 < 4; t4++) {
                int nn = t4 * 16 + brow;
                LDSM4(kb4[2*t4][0], kb4[2*t4][1], kb4[2*t4+1][0], kb4[2*t4+1][1],
                      sKs + (uint32_t)((nn * FFS + kk * 16 + bcol) * 2));
            }
            #pragma unroll
            for (int t = 0; t < 8; t++)
                mma16816(sacc[t], qf[kk], kb4[t][0], kb4[t][1]);
        }

        // ---- P = ex2(s*0.125*log2e + madd') -> register A-frags; row sums ----
        const int j0 = j * 64;
        float ls0 = 0.f, ls1 = 0.f;
        uint32_t pa[4][4];
        #pragma unroll
        for (int t = 0; t < 8; t++) {
            float2 md = *reinterpret_cast<const float2*>(&Madd[j0 + t * 8 + c2]);
            float p0 = ex2(fmaf(sacc[t][0], SC2, md.x));
            float p1 = ex2(fmaf(sacc[t][1], SC2, md.y));
            float p2 = ex2(fmaf(sacc[t][2], SC2, md.x));
            float p3 = ex2(fmaf(sacc[t][3], SC2, md.y));
            ls0 += p0 + p1;
            ls1 += p2 + p3;
            int kk = t >> 1;
            if ((t & 1) == 0) { pa[kk][0] = bf2(p0, p1); pa[kk][1] = bf2(p2, p3); }
            else              { pa[kk][2] = bf2(p0, p1); pa[kk][3] = bf2(p2, p3); }
        }
        ls0 += __shfl_xor_sync(0xffffffffu, ls0, 1);
        ls0 += __shfl_xor_sync(0xffffffffu, ls0, 2);
        ls1 += __shfl_xor_sync(0xffffffffu, ls1, 1);
        ls1 += __shfl_xor_sync(0xffffffffu, ls1, 2);
        lrow0 += ls0;
        lrow1 += ls1;

        // ---- ctx += P @ V : 16 rows x 64 dh ----
        const uint32_t sVs = sb + (uint32_t)((FV + s * 64 * FFS) * 2);
        #pragma unroll
        for (int kk = 0; kk < 4; kk++) {
            uint32_t vb4[8][2];
            #pragma unroll
            for (int t4 = 0; t4 < 4; t4++) {
                int kr = kk * 16 + tkrow;
                int nc = t4 * 16 + tncol;
                LDSM4T(vb4[2*t4][0], vb4[2*t4][1], vb4[2*t4+1][0], vb4[2*t4+1][1],
                       sVs + (uint32_t)((kr * FFS + nc) * 2));
            }
            #pragma unroll
            for (int t = 0; t < 8; t++)
                mma16816(ctxa[t], pa[kk], vb4[t][0], vb4[t][1]);
        }
        s++; if (s == 3) s = 0;
    }

    // ---- finalize ----
    float inv0 = 1.0f / lrow0, inv1 = 1.0f / lrow1;
    size_t r0g = ((size_t)bb * SS_ + q0 + mrow0 + gr) * HID_ + hh * 64;
    size_t r1g = r0g + 8 * HID_;
    #pragma unroll
    for (int t = 0; t < 8; t++) {
        int col = t * 8 + c2;
        *reinterpret_cast<uint32_t*>(ctx + r0g + col) = bf2(ctxa[t][0] * inv0, ctxa[t][1] * inv0);
        *reinterpret_cast<uint32_t*>(ctx + r1g + col) = bf2(ctxa[t][2] * inv1, ctxa[t][3] * inv1);
    }
}

// ---------------- bf16 mma GEMM (R10 proven config) ----------------
// EPI: 0 = +bias -> bf16; 2 = gelu(+bias) -> bf16; 3 = +bias+residual -> fp32
template<int EPI>
__global__ __launch_bounds__(256, 2) void tc_gemm(
    int M, int N, int K,
    const __nv_bfloat16* __restrict__ A,  int lda,
    const __nv_bfloat16* __restrict__ Bm, int ldb,
    float* __restrict__ Cf, __nv_bfloat16* __restrict__ Cb, int ldc,
    const float* __restrict__ bias, const float* __restrict__ residual)
{
    constexpr int RS  = 72;
    constexpr int ASZ = 128 * RS;
    constexpr int STG = 2 * ASZ;
    constexpr int NT  = 4;

    extern __shared__ __align__(16) char smc[];

    const int tid  = threadIdx.x;
    const int wid  = tid >> 5, lane = tid & 31;
    const int wm   = wid >> 2, wn = wid & 3;
    const int qq   = lane >> 3, l8 = lane & 7;
    const int arow = ((qq & 1) << 3) + l8, acol = (qq >> 1) << 3;
    const int brow = ((qq >> 1) << 3) + l8, bcol = (qq & 1) << 3;
    const int row0 = blockIdx.y * 128;
    const int col0 = blockIdx.x * 128;

    const uint32_t sbase = smem_u32(smc);

    float acc[4][NT][4];
    #pragma unroll
    for (int i = 0; i < 4; i++)
        #pragma unroll
        for (int j = 0; j < NT; j++)
            #pragma unroll
            for (int e = 0; e < 4; e++) acc[i][j][e] = 0.0f;

    const int nk = K >> 6;

    auto load_stage = [&](int i, int s) {
        const int k0 = i << 6;
        uint32_t abase = sbase + (uint32_t)(s * STG) * 2u;
        uint32_t bbase = abase + (uint32_t)ASZ * 2u;
        #pragma unroll
        for (int u = 0; u < 4; u++) {
            int idx = tid + u * 256;
            int r = idx >> 3, c8 = (idx & 7) << 3;
            CP16(abase + (uint32_t)(r * RS + c8) * 2u,
                 A + (size_t)(row0 + r) * lda + k0 + c8);
        }
        #pragma unroll
        for (int u = 0; u < 4; u++) {
            int idx = tid + u * 256;
            int r = idx >> 3, c8 = (idx & 7) << 3;
            CP16(bbase + (uint32_t)(r * RS + c8) * 2u,
                 Bm + (size_t)(col0 + r) * ldb + k0 + c8);
        }
        CP_COMMIT();
    };

    load_stage(0, 0);
    load_stage(1, 1);

    int s = 0;
    for (int i = 0; i < nk; i++) {
        if (i == nk - 1) { CP_WAIT0(); } else { CP_WAIT1(); }
        __syncthreads();
        int ns = s + 2; if (ns >= 3) ns -= 3;
        if (i + 2 < nk) load_stage(i + 2, ns);

        const uint32_t sAs = sbase + (uint32_t)(s * STG) * 2u;
        const uint32_t sBs = sAs + (uint32_t)ASZ * 2u;

        #pragma unroll
        for (int kk = 0; kk < 4; kk++) {
            uint32_t af[4][4];
            #pragma unroll
            for (int mt = 0; mt < 4; mt++) {
                int rr = wm * 64 + mt * 16 + arow;
                LDSM4(af[mt][0], af[mt][1], af[mt][2], af[mt][3],
                      sAs + (uint32_t)((rr * RS + kk * 16 + acol) * 2));
            }
            uint32_t bf[NT][2];
            #pragma unroll
            for (int ntp = 0; ntp < NT / 2; ntp++) {
                int nn = wn * 32 + ntp * 16 + brow;
                LDSM4(bf[2*ntp][0], bf[2*ntp][1], bf[2*ntp+1][0], bf[2*ntp+1][1],
                      sBs + (uint32_t)((nn * RS + kk * 16 + bcol) * 2));
            }
            #pragma unroll
            for (int nt = 0; nt < NT; nt++)
                #pragma unroll
                for (int mt = 0; mt < 4; mt++)
                    mma16816(acc[mt][nt], af[mt], bf[nt][0], bf[nt][1]);
        }
        s++; if (s == 3) s = 0;
    }

    #pragma unroll
    for (int mt = 0; mt < 4; mt++) {
        #pragma unroll
        for (int nt = 0; nt < NT; nt++) {
            int r0 = row0 + wm * 64 + mt * 16 + (lane >> 2);
            int c0 = col0 + wn * 32 + nt * 8 + 2 * (lane & 3);
            #pragma unroll
            for (int half = 0; half < 2; half++) {
                int r = r0 + half * 8;
                float v0 = acc[mt][nt][2 * half + 0];
                float v1 = acc[mt][nt][2 * half + 1];
                v0 += __ldg(&bias[c0]);
                v1 += __ldg(&bias[c0 + 1]);
                if (EPI == 2) {
                    v0 = 0.5f * v0 * (1.0f + erff(v0 * 0.70710678118654752f));
                    v1 = 0.5f * v1 * (1.0f + erff(v1 * 0.70710678118654752f));
                }
                if (EPI == 3) {
                    float2 rr = *reinterpret_cast<const float2*>(
                        residual + (size_t)r * ldc + c0);
                    v0 += rr.x; v1 += rr.y;
                    float2 o; o.x = v0; o.y = v1;
                    *reinterpret_cast<float2*>(Cf + (size_t)r * ldc + c0) = o;
                } else {
                    *reinterpret_cast<uint32_t*>(Cb + (size_t)r * ldc + c0) = bf2(v0, v1);
                }
            }
        }
    }
}

// ---------------- launch ----------------
extern "C" void kernel_launch(void* const* d_in, const int* in_sizes, int n_in,
                              void* d_out, int out_size) {
    const float* x   = (const float*)d_in[0];
    const float* am  = (const float*)d_in[1];
    const float* Wq  = (const float*)d_in[2];
    const float* bq  = (const float*)d_in[3];
    const float* Wk  = (const float*)d_in[4];
    const float* bk  = (const float*)d_in[5];
    const float* Wv  = (const float*)d_in[6];
    const float* bv  = (const float*)d_in[7];
    const float* Wo  = (const float*)d_in[8];
    const float* bo  = (const float*)d_in[9];
    const float* W1  = (const float*)d_in[10];
    const float* b1  = (const float*)d_in[11];
    const float* W2  = (const float*)d_in[12];
    const float* b2  = (const float*)d_in[13];
    const float* g1  = (const float*)d_in[14];
    const float* be1 = (const float*)d_in[15];
    const float* g2  = (const float*)d_in[16];
    const float* be2 = (const float*)d_in[17];
    float* out = (float*)d_out;

    __nv_bfloat16 *h, *qkv, *ctx, *h2, *ff, *wb;
    float *x2, *bqkv;
    cudaGetSymbolAddress((void**)&h,    g_h);
    cudaGetSymbolAddress((void**)&qkv,  g_qkv);
    cudaGetSymbolAddress((void**)&ctx,  g_ctx);
    cudaGetSymbolAddress((void**)&x2,   g_x2);
    cudaGetSymbolAddress((void**)&h2,   g_h2);
    cudaGetSymbolAddress((void**)&ff,   g_ff);
    cudaGetSymbolAddress((void**)&wb,   g_wb);
    cudaGetSymbolAddress((void**)&bqkv, g_bqkv);

    __nv_bfloat16* rWqkv = wb;
    __nv_bfloat16* rWo = wb + 3 * 1024 * 1024;
    __nv_bfloat16* rW1 = wb + 4 * 1024 * 1024;
    __nv_bfloat16* rW2 = wb + 8 * 1024 * 1024;

    const int SM3 = 3 * 2 * 128 * 72 * 2;            // 110592 bytes
    cudaFuncSetAttribute(tc_gemm<0>, cudaFuncAttributeMaxDynamicSharedMemorySize, SM3);
    cudaFuncSetAttribute(tc_gemm<2>, cudaFuncAttributeMaxDynamicSharedMemorySize, SM3);
    cudaFuncSetAttribute(tc_gemm<3>, cudaFuncAttributeMaxDynamicSharedMemorySize, SM3);
    cudaFuncSetAttribute(flash_kernel, cudaFuncAttributeMaxDynamicSharedMemorySize, FL_SMEM);

    dim3 blk(256);

    convert_all_kernel<<<12300, blk>>>(Wq, Wk, Wv, Wo, W1, W2, bq, bk, bv, wb, bqkv);
    ln_kernel<<<TOK_, blk>>>(x, g1, be1, h);
    tc_gemm<0><<<dim3(QKVLD/128, TOK_/128), blk, SM3>>>(TOK_, QKVLD, HID_,
        h, HID_,  rWqkv, HID_,  nullptr, qkv, QKVLD,  bqkv, nullptr);
    flash_kernel<<<dim3(SS_/128, BB_*NH_), blk, FL_SMEM>>>(qkv, am, ctx);
    tc_gemm<3><<<dim3(HID_/128, TOK_/128), blk, SM3>>>(TOK_, HID_, HID_,
        ctx, HID_,  rWo, HID_,  x2, nullptr, HID_,  bo, x);
    ln_kernel<<<TOK_, blk>>>(x2, g2, be2, h2);
    tc_gemm<2><<<dim3(FF_/128, TOK_/128), blk, SM3>>>(TOK_, FF_, HID_,
        h2, HID_,  rW1, HID_,  nullptr, ff, FF_,  b1, nullptr);
    tc_gemm<3><<<dim3(HID_/128, TOK_/128), blk, SM3>>>(TOK_, HID_, FF_,
        ff, FF_,  rW2, FF_,  out, nullptr, HID_,  b2, x2);
}

// round 17
// speedup vs baseline: 1.0313x; 1.0021x over previous
#include <cuda_runtime.h>
#include <cuda_bf16.h>
#include <math.h>
#include <stdint.h>

#define BB_   2
#define SS_   2048
#define HID_  1024
#define NH_   16
#define HD_   64
#define FF_   4096
#define TOK_  (BB_*SS_)   // 4096
#define QKVLD 3072
#define LOG2E 1.4426950408889634f

// ---------------- scratch ----------------
__device__ __nv_bfloat16 g_h  [TOK_*HID_];
__device__ __nv_bfloat16 g_qkv[TOK_*3*HID_];       // [TOK, 3072] = q|k|v
__device__ __nv_bfloat16 g_ctx[TOK_*HID_];
__device__ float         g_x2 [TOK_*HID_];
__device__ __nv_bfloat16 g_h2 [TOK_*HID_];
__device__ __nv_bfloat16 g_ff [TOK_*FF_];
__device__ __nv_bfloat16 g_wb [12*1024*1024];      // bf16 weights (q|k|v|o|W1|W2)
__device__ float         g_bqkv[3*HID_];

// ---------------- helpers ----------------
__device__ __forceinline__ uint32_t bf2(float x, float y) {
    __nv_bfloat162 t = __floats2bfloat162_rn(x, y);
    return *reinterpret_cast<uint32_t*>(&t);
}
__device__ __forceinline__ float ex2(float x) {
    float y;
    asm("ex2.approx.f32 %0, %1;" : "=f"(y) : "f"(x));
    return y;
}
__device__ __forceinline__ uint32_t smem_u32(const void* p) {
    uint32_t a;
    asm("{ .reg .u64 t; cvta.to.shared.u64 t, %1; cvt.u32.u64 %0, t; }" : "=r"(a) : "l"(p));
    return a;
}
#define CP16(dst, src) \
    asm volatile("cp.async.cg.shared.global [%0], [%1], 16;" :: "r"(dst), "l"(src) : "memory")
#define CP_COMMIT() asm volatile("cp.async.commit_group;" ::: "memory")
#define CP_WAIT2()  asm volatile("cp.async.wait_group 2;" ::: "memory")
#define CP_WAIT1()  asm volatile("cp.async.wait_group 1;" ::: "memory")
#define CP_WAIT0()  asm volatile("cp.async.wait_group 0;" ::: "memory")

#define LDSM4(R0, R1, R2, R3, ADDR) \
    asm volatile("ldmatrix.sync.aligned.m8n8.x4.shared.b16 {%0,%1,%2,%3}, [%4];" \
        : "=r"(R0), "=r"(R1), "=r"(R2), "=r"(R3) : "r"(ADDR))
#define LDSM4T(R0, R1, R2, R3, ADDR) \
    asm volatile("ldmatrix.sync.aligned.m8n8.x4.trans.shared.b16 {%0,%1,%2,%3}, [%4];" \
        : "=r"(R0), "=r"(R1), "=r"(R2), "=r"(R3) : "r"(ADDR))

__device__ __forceinline__ void mma16816(float* c, const uint32_t* a, uint32_t b0, uint32_t b1) {
    asm volatile(
        "mma.sync.aligned.m16n8k16.row.col.f32.bf16.bf16.f32 "
        "{%0,%1,%2,%3}, {%4,%5,%6,%7}, {%8,%9}, {%0,%1,%2,%3};"
        : "+f"(c[0]), "+f"(c[1]), "+f"(c[2]), "+f"(c[3])
        : "r"(a[0]), "r"(a[1]), "r"(a[2]), "r"(a[3]), "r"(b0), "r"(b1));
}

// ---------------- block reduction ----------------
template<bool MAX>
__device__ __forceinline__ float block_reduce_256(float v) {
    __shared__ float sh[8];
    int lane = threadIdx.x & 31, w = threadIdx.x >> 5;
    #pragma unroll
    for (int o = 16; o; o >>= 1) {
        float u = __shfl_xor_sync(0xffffffffu, v, o);
        v = MAX ? fmaxf(v, u) : v + u;
    }
    if (lane == 0) sh[w] = v;
    __syncthreads();
    if (w == 0) {
        v = sh[lane & 7];
        #pragma unroll
        for (int o = 4; o; o >>= 1) {
            float u = __shfl_xor_sync(0xffffffffu, v, o);
            v = MAX ? fmaxf(v, u) : v + u;
        }
        if (lane == 0) sh[0] = v;
    }
    __syncthreads();
    float r = sh[0];
    __syncthreads();
    return r;
}

__device__ __forceinline__ void ln_row(const float* __restrict__ x,
                                       const float* __restrict__ g,
                                       const float* __restrict__ beta,
                                       __nv_bfloat16* __restrict__ out, int row) {
    size_t base = (size_t)row * HID_;
    const float4* xp = reinterpret_cast<const float4*>(x + base);
    int t = threadIdx.x;
    float4 v = xp[t];
    float s = v.x + v.y + v.z + v.w;
    s = block_reduce_256<false>(s);
    float mean = s * (1.0f / HID_);
    float dx = v.x - mean, dy = v.y - mean, dz = v.z - mean, dw = v.w - mean;
    float q = dx*dx + dy*dy + dz*dz + dw*dw;
    q = block_reduce_256<false>(q);
    float r = rsqrtf(q * (1.0f / HID_) + 1e-5f);
    float4 gv = reinterpret_cast<const float4*>(g)[t];
    float4 bv = reinterpret_cast<const float4*>(beta)[t];
    uint2 o;
    o.x = bf2(dx * r * gv.x + bv.x, dy * r * gv.y + bv.y);
    o.y = bf2(dz * r * gv.z + bv.z, dw * r * gv.w + bv.w);
    reinterpret_cast<uint2*>(out + base)[t] = o;
}

// ---------------- fused: weight conversion + bias pack + LN1 (one launch) ----------------
// blocks [0,4096): Wq|Wk|Wv|Wo ; [4096,12288): W1|W2 ; [12288,12300): bias pack ;
// [12300,16396): LN1 rows
__global__ void convert_all_kernel(
    const float* __restrict__ Wq, const float* __restrict__ Wk,
    const float* __restrict__ Wv, const float* __restrict__ Wo,
    const float* __restrict__ W1, const float* __restrict__ W2,
    const float* __restrict__ bq, const float* __restrict__ bk,
    const float* __restrict__ bv,
    const float* __restrict__ x,  const float* __restrict__ g1,
    const float* __restrict__ be1,
    __nv_bfloat16* __restrict__ wb, float* __restrict__ bqkv,
    __nv_bfloat16* __restrict__ h)
{
    int bid = blockIdx.x;
    if (bid < 4096) {
        int i = bid * 256 + threadIdx.x;
        int seg = i >> 18, off = i & 262143;
        const float4* sp;
        __nv_bfloat16* dp;
        if      (seg == 0) { sp = (const float4*)Wq; dp = wb; }
        else if (seg == 1) { sp = (const float4*)Wk; dp = wb + 1024*1024; }
        else if (seg == 2) { sp = (const float4*)Wv; dp = wb + 2*1024*1024; }
        else               { sp = (const float4*)Wo; dp = wb + 3*1024*1024; }
        float4 v = sp[off];
        reinterpret_cast<uint2*>(dp)[off] = make_uint2(bf2(v.x, v.y), bf2(v.z, v.w));
    } else if (bid < 12288) {
        int i = (bid - 4096) * 256 + threadIdx.x;
        int seg = i >> 20, off = i & 1048575;
        const float4* sp = seg ? (const float4*)W2 : (const float4*)W1;
        __nv_bfloat16* dp = seg ? (wb + 8*1024*1024) : (wb + 4*1024*1024);
        float4 v = sp[off];
        reinterpret_cast<uint2*>(dp)[off] = make_uint2(bf2(v.x, v.y), bf2(v.z, v.w));
    } else if (bid < 12300) {
        int i = (bid - 12288) * 256 + threadIdx.x;
        if (i < HID_)            bqkv[i] = bq[i];
        else if (i < 2 * HID_)   bqkv[i] = bk[i - HID_];
        else if (i < 3 * HID_)   bqkv[i] = bv[i - 2 * HID_];
    } else {
        ln_row(x, g1, be1, h, bid - 12300);
    }
}

// ---------------- standalone LN (for LN2) ----------------
__global__ void ln_kernel(const float* __restrict__ x, const float* __restrict__ g,
                          const float* __restrict__ beta, __nv_bfloat16* __restrict__ out) {
    ln_row(x, g, beta, out, blockIdx.x);
}

// ---------------- flash attention: R16 config (register P, M-partitioned warps,
// 3-stage KV ring, 1 barrier/iter, exp2-folded softmax) ----------------
#define FFS 72
#define FQ  0
#define FK  (128*FFS)
#define FV  (FK + 3*64*FFS)
#define FL_FLT ((FV + 3*64*FFS) * 2)
#define FL_SMEM (FL_FLT + 2048 * 4)
#define SC2 (0.125f * LOG2E)

__global__ __launch_bounds__(256, 2) void flash_kernel(
    const __nv_bfloat16* __restrict__ qkv,
    const float* __restrict__ am, __nv_bfloat16* __restrict__ ctx)
{
    extern __shared__ __align__(16) char smc[];
    float* Madd = reinterpret_cast<float*>(smc + FL_FLT);

    const int tid = threadIdx.x, lane = tid & 31, wid = tid >> 5;   // wid 0..7
    const int gr = lane >> 2, c2 = (lane & 3) << 1;
    const int qq = lane >> 3, l8 = lane & 7;
    const int arow = ((qq & 1) << 3) + l8, acol = (qq >> 1) << 3;
    const int brow = ((qq >> 1) << 3) + l8, bcol = (qq & 1) << 3;
    const int tkrow = ((qq & 1) << 3) + l8, tncol = (qq >> 1) << 3;
    const int qt = blockIdx.x, bh = blockIdx.y;
    const int bb = bh >> 4, hh = bh & 15;
    const int q0 = qt * 128;
    const int mrow0 = wid * 16;

    const __nv_bfloat16* Qg = qkv + ((size_t)bb * SS_ + q0) * QKVLD + hh * 64;
    const __nv_bfloat16* Kg = qkv + (size_t)bb * SS_ * QKVLD + HID_ + hh * 64;
    const __nv_bfloat16* Vg = qkv + (size_t)bb * SS_ * QKVLD + 2 * HID_ + hh * 64;

    const uint32_t sb = smem_u32(smc);
    const uint32_t sQ = sb + FQ * 2;

    // stage Q (128x64) — own group
    #pragma unroll
    for (int u = 0; u < 4; u++) {
        int idx = tid + u * 256;
        int r = idx >> 3, c8 = (idx & 7) << 3;
        CP16(sQ + (uint32_t)((r * FFS + c8) * 2), Qg + (size_t)r * QKVLD + c8);
    }
    CP_COMMIT();
    // mask-add, pre-scaled by log2e (feeds ex2 directly)
    #pragma unroll
    for (int u = 0; u < 8; u++) {
        int i = tid + u * 256;
        Madd[i] = (__ldg(&am[(size_t)bb * SS_ + i]) - 1.0f) * (10000.0f * LOG2E);
    }

    auto load_kv = [&](int j, int s) {
        const int j0 = j * 64;
        uint32_t kb = sb + (uint32_t)((FK + s * 64 * FFS) * 2);
        uint32_t vb = sb + (uint32_t)((FV + s * 64 * FFS) * 2);
        #pragma unroll
        for (int u = 0; u < 2; u++) {
            int idx = tid + u * 256;
            int r = idx >> 3, c8 = (idx & 7) << 3;
            CP16(kb + (uint32_t)((r * FFS + c8) * 2), Kg + (size_t)(j0 + r) * QKVLD + c8);
        }
        #pragma unroll
        for (int u = 0; u < 2; u++) {
            int idx = tid + u * 256;
            int r = idx >> 3, c8 = (idx & 7) << 3;
            CP16(vb + (uint32_t)((r * FFS + c8) * 2), Vg + (size_t)(j0 + r) * QKVLD + c8);
        }
        CP_COMMIT();
    };
    load_kv(0, 0);
    load_kv(1, 1);

    // hoist Q fragments
    CP_WAIT2();
    __syncthreads();
    uint32_t qf[4][4];
    #pragma unroll
    for (int kk = 0; kk < 4; kk++) {
        int rr = mrow0 + arow;
        LDSM4(qf[kk][0], qf[kk][1], qf[kk][2], qf[kk][3],
              sQ + (uint32_t)((rr * FFS + kk * 16 + acol) * 2));
    }

    float ctxa[8][4] = {};
    float lrow0 = 0.f, lrow1 = 0.f;

    const int IT = SS_ / 64;   // 32
    int s = 0;
    for (int j = 0; j < IT; j++) {
        if (j == IT - 1) { CP_WAIT0(); } else { CP_WAIT1(); }
        __syncthreads();
        int ns = s + 2; if (ns >= 3) ns -= 3;
        if (j + 2 < IT) load_kv(j + 2, ns);

        // ---- S = Q @ K^T : 16 rows x 64 keys ----
        float sacc[8][4] = {};
        const uint32_t sKs = sb + (uint32_t)((FK + s * 64 * FFS) * 2);
        #pragma unroll
        for (int kk = 0; kk < 4; kk++) {
            uint32_t kb4[8][2];
            #pragma unroll
            for (int t4 = 0; t4 < 4; t4++) {
                int nn = t4 * 16 + brow;
                LDSM4(kb4[2*t4][0], kb4[2*t4][1], kb4[2*t4+1][0], kb4[2*t4+1][1],
                      sKs + (uint32_t)((nn * FFS + kk * 16 + bcol) * 2));
            }
            #pragma unroll
            for (int t = 0; t < 8; t++)
                mma16816(sacc[t], qf[kk], kb4[t][0], kb4[t][1]);
        }

        // ---- P = ex2(s*0.125*log2e + madd') -> register A-frags; row sums ----
        const int j0 = j * 64;
        float ls0 = 0.f, ls1 = 0.f;
        uint32_t pa[4][4];
        #pragma unroll
        for (int t = 0; t < 8; t++) {
            float2 md = *reinterpret_cast<const float2*>(&Madd[j0 + t * 8 + c2]);
            float p0 = ex2(fmaf(sacc[t][0], SC2, md.x));
            float p1 = ex2(fmaf(sacc[t][1], SC2, md.y));
            float p2 = ex2(fmaf(sacc[t][2], SC2, md.x));
            float p3 = ex2(fmaf(sacc[t][3], SC2, md.y));
            ls0 += p0 + p1;
            ls1 += p2 + p3;
            int kk = t >> 1;
            if ((t & 1) == 0) { pa[kk][0] = bf2(p0, p1); pa[kk][1] = bf2(p2, p3); }
            else              { pa[kk][2] = bf2(p0, p1); pa[kk][3] = bf2(p2, p3); }
        }
        ls0 += __shfl_xor_sync(0xffffffffu, ls0, 1);
        ls0 += __shfl_xor_sync(0xffffffffu, ls0, 2);
        ls1 += __shfl_xor_sync(0xffffffffu, ls1, 1);
        ls1 += __shfl_xor_sync(0xffffffffu, ls1, 2);
        lrow0 += ls0;
        lrow1 += ls1;

        // ---- ctx += P @ V : 16 rows x 64 dh ----
        const uint32_t sVs = sb + (uint32_t)((FV + s * 64 * FFS) * 2);
        #pragma unroll
        for (int kk = 0; kk < 4; kk++) {
            uint32_t vb4[8][2];
            #pragma unroll
            for (int t4 = 0; t4 < 4; t4++) {
                int kr = kk * 16 + tkrow;
                int nc = t4 * 16 + tncol;
                LDSM4T(vb4[2*t4][0], vb4[2*t4][1], vb4[2*t4+1][0], vb4[2*t4+1][1],
                       sVs + (uint32_t)((kr * FFS + nc) * 2));
            }
            #pragma unroll
            for (int t = 0; t < 8; t++)
                mma16816(ctxa[t], pa[kk], vb4[t][0], vb4[t][1]);
        }
        s++; if (s == 3) s = 0;
    }

    // ---- finalize ----
    float inv0 = 1.0f / lrow0, inv1 = 1.0f / lrow1;
    size_t r0g = ((size_t)bb * SS_ + q0 + mrow0 + gr) * HID_ + hh * 64;
    size_t r1g = r0g + 8 * HID_;
    #pragma unroll
    for (int t = 0; t < 8; t++) {
        int col = t * 8 + c2;
        *reinterpret_cast<uint32_t*>(ctx + r0g + col) = bf2(ctxa[t][0] * inv0, ctxa[t][1] * inv0);
        *reinterpret_cast<uint32_t*>(ctx + r1g + col) = bf2(ctxa[t][2] * inv1, ctxa[t][3] * inv1);
    }
}

// ---------------- bf16 mma GEMM (R10 proven config; hoisted bias loads) ----------------
// EPI: 0 = +bias -> bf16; 2 = gelu(+bias) -> bf16; 3 = +bias+residual -> fp32
template<int EPI>
__global__ __launch_bounds__(256, 2) void tc_gemm(
    int M, int N, int K,
    const __nv_bfloat16* __restrict__ A,  int lda,
    const __nv_bfloat16* __restrict__ Bm, int ldb,
    float* __restrict__ Cf, __nv_bfloat16* __restrict__ Cb, int ldc,
    const float* __restrict__ bias, const float* __restrict__ residual)
{
    constexpr int RS  = 72;
    constexpr int ASZ = 128 * RS;
    constexpr int STG = 2 * ASZ;
    constexpr int NT  = 4;

    extern __shared__ __align__(16) char smc[];

    const int tid  = threadIdx.x;
    const int wid  = tid >> 5, lane = tid & 31;
    const int wm   = wid >> 2, wn = wid & 3;
    const int qq   = lane >> 3, l8 = lane & 7;
    const int arow = ((qq & 1) << 3) + l8, acol = (qq >> 1) << 3;
    const int brow = ((qq >> 1) << 3) + l8, bcol = (qq & 1) << 3;
    const int row0 = blockIdx.y * 128;
    const int col0 = blockIdx.x * 128;

    const uint32_t sbase = smem_u32(smc);

    float acc[4][NT][4];
    #pragma unroll
    for (int i = 0; i < 4; i++)
        #pragma unroll
        for (int j = 0; j < NT; j++)
            #pragma unroll
            for (int e = 0; e < 4; e++) acc[i][j][e] = 0.0f;

    const int nk = K >> 6;

    auto load_stage = [&](int i, int s) {
        const int k0 = i << 6;
        uint32_t abase = sbase + (uint32_t)(s * STG) * 2u;
        uint32_t bbase = abase + (uint32_t)ASZ * 2u;
        #pragma unroll
        for (int u = 0; u < 4; u++) {
            int idx = tid + u * 256;
            int r = idx >> 3, c8 = (idx & 7) << 3;
            CP16(abase + (uint32_t)(r * RS + c8) * 2u,
                 A + (size_t)(row0 + r) * lda + k0 + c8);
        }
        #pragma unroll
        for (int u = 0; u < 4; u++) {
            int idx = tid + u * 256;
            int r = idx >> 3, c8 = (idx & 7) << 3;
            CP16(bbase + (uint32_t)(r * RS + c8) * 2u,
                 Bm + (size_t)(col0 + r) * ldb + k0 + c8);
        }
        CP_COMMIT();
    };

    load_stage(0, 0);
    load_stage(1, 1);

    int s = 0;
    for (int i = 0; i < nk; i++) {
        if (i == nk - 1) { CP_WAIT0(); } else { CP_WAIT1(); }
        __syncthreads();
        int ns = s + 2; if (ns >= 3) ns -= 3;
        if (i + 2 < nk) load_stage(i + 2, ns);

        const uint32_t sAs = sbase + (uint32_t)(s * STG) * 2u;
        const uint32_t sBs = sAs + (uint32_t)ASZ * 2u;

        #pragma unroll
        for (int kk = 0; kk < 4; kk++) {
            uint32_t af[4][4];
            #pragma unroll
            for (int mt = 0; mt < 4; mt++) {
                int rr = wm * 64 + mt * 16 + arow;
                LDSM4(af[mt][0], af[mt][1], af[mt][2], af[mt][3],
                      sAs + (uint32_t)((rr * RS + kk * 16 + acol) * 2));
            }
            uint32_t bf[NT][2];
            #pragma unroll
            for (int ntp = 0; ntp < NT / 2; ntp++) {
                int nn = wn * 32 + ntp * 16 + brow;
                LDSM4(bf[2*ntp][0], bf[2*ntp][1], bf[2*ntp+1][0], bf[2*ntp+1][1],
                      sBs + (uint32_t)((nn * RS + kk * 16 + bcol) * 2));
            }
            #pragma unroll
            for (int nt = 0; nt < NT; nt++)
                #pragma unroll
                for (int mt = 0; mt < 4; mt++)
                    mma16816(acc[mt][nt], af[mt], bf[nt][0], bf[nt][1]);
        }
        s++; if (s == 3) s = 0;
    }

    // epilogue — bias loaded once per nt (c0 independent of mt/half)
    #pragma unroll
    for (int nt = 0; nt < NT; nt++) {
        int c0 = col0 + wn * 32 + nt * 8 + 2 * (lane & 3);
        float b0 = __ldg(&bias[c0]);
        float b1 = __ldg(&bias[c0 + 1]);
        #pragma unroll
        for (int mt = 0; mt < 4; mt++) {
            int r0 = row0 + wm * 64 + mt * 16 + (lane >> 2);
            #pragma unroll
            for (int half = 0; half < 2; half++) {
                int r = r0 + half * 8;
                float v0 = acc[mt][nt][2 * half + 0] + b0;
                float v1 = acc[mt][nt][2 * half + 1] + b1;
                if (EPI == 2) {
                    v0 = 0.5f * v0 * (1.0f + erff(v0 * 0.70710678118654752f));
                    v1 = 0.5f * v1 * (1.0f + erff(v1 * 0.70710678118654752f));
                }
                if (EPI == 3) {
                    float2 rr = *reinterpret_cast<const float2*>(
                        residual + (size_t)r * ldc + c0);
                    v0 += rr.x; v1 += rr.y;
                    float2 o; o.x = v0; o.y = v1;
                    *reinterpret_cast<float2*>(Cf + (size_t)r * ldc + c0) = o;
                } else {
                    *reinterpret_cast<uint32_t*>(Cb + (size_t)r * ldc + c0) = bf2(v0, v1);
                }
            }
        }
    }
}

// ---------------- launch ----------------
extern "C" void kernel_launch(void* const* d_in, const int* in_sizes, int n_in,
                              void* d_out, int out_size) {
    const float* x   = (const float*)d_in[0];
    const float* am  = (const float*)d_in[1];
    const float* Wq  = (const float*)d_in[2];
    const float* bq  = (const float*)d_in[3];
    const float* Wk  = (const float*)d_in[4];
    const float* bk  = (const float*)d_in[5];
    const float* Wv  = (const float*)d_in[6];
    const float* bv  = (const float*)d_in[7];
    const float* Wo  = (const float*)d_in[8];
    const float* bo  = (const float*)d_in[9];
    const float* W1  = (const float*)d_in[10];
    const float* b1  = (const float*)d_in[11];
    const float* W2  = (const float*)d_in[12];
    const float* b2  = (const float*)d_in[13];
    const float* g1  = (const float*)d_in[14];
    const float* be1 = (const float*)d_in[15];
    const float* g2  = (const float*)d_in[16];
    const float* be2 = (const float*)d_in[17];
    float* out = (float*)d_out;

    __nv_bfloat16 *h, *qkv, *ctx, *h2, *ff, *wb;
    float *x2, *bqkv;
    cudaGetSymbolAddress((void**)&h,    g_h);
    cudaGetSymbolAddress((void**)&qkv,  g_qkv);
    cudaGetSymbolAddress((void**)&ctx,  g_ctx);
    cudaGetSymbolAddress((void**)&x2,   g_x2);
    cudaGetSymbolAddress((void**)&h2,   g_h2);
    cudaGetSymbolAddress((void**)&ff,   g_ff);
    cudaGetSymbolAddress((void**)&wb,   g_wb);
    cudaGetSymbolAddress((void**)&bqkv, g_bqkv);

    __nv_bfloat16* rWqkv = wb;
    __nv_bfloat16* rWo = wb + 3 * 1024 * 1024;
    __nv_bfloat16* rW1 = wb + 4 * 1024 * 1024;
    __nv_bfloat16* rW2 = wb + 8 * 1024 * 1024;

    const int SM3 = 3 * 2 * 128 * 72 * 2;            // 110592 bytes
    cudaFuncSetAttribute(tc_gemm<0>, cudaFuncAttributeMaxDynamicSharedMemorySize, SM3);
    cudaFuncSetAttribute(tc_gemm<2>, cudaFuncAttributeMaxDynamicSharedMemorySize, SM3);
    cudaFuncSetAttribute(tc_gemm<3>, cudaFuncAttributeMaxDynamicSharedMemorySize, SM3);
    cudaFuncSetAttribute(flash_kernel, cudaFuncAttributeMaxDynamicSharedMemorySize, FL_SMEM);

    dim3 blk(256);

    // 0: weight conversion + bias pack + LN1 in one launch
    convert_all_kernel<<<12300 + TOK_, blk>>>(Wq, Wk, Wv, Wo, W1, W2, bq, bk, bv,
                                              x, g1, be1, wb, bqkv, h);
    // 1: qkv
    tc_gemm<0><<<dim3(QKVLD/128, TOK_/128), blk, SM3>>>(TOK_, QKVLD, HID_,
        h, HID_,  rWqkv, HID_,  nullptr, qkv, QKVLD,  bqkv, nullptr);
    // 2: fused attention
    flash_kernel<<<dim3(SS_/128, BB_*NH_), blk, FL_SMEM>>>(qkv, am, ctx);
    // 3: x2 = x + ctx @ Wo^T + bo
    tc_gemm<3><<<dim3(HID_/128, TOK_/128), blk, SM3>>>(TOK_, HID_, HID_,
        ctx, HID_,  rWo, HID_,  x2, nullptr, HID_,  bo, x);
    // 4: h2 = LN2(x2)
    ln_kernel<<<TOK_, blk>>>(x2, g2, be2, h2);
    // 5: ff = gelu(h2 @ W1^T + b1)
    tc_gemm<2><<<dim3(FF_/128, TOK_/128), blk, SM3>>>(TOK_, FF_, HID_,
        h2, HID_,  rW1, HID_,  nullptr, ff, FF_,  b1, nullptr);
    // 6: out = x2 + ff @ W2^T + b2
    tc_gemm<3><<<dim3(HID_/128, TOK_/128), blk, SM3>>>(TOK_, HID_, FF_,
        ff, FF_,  rW2, FF_,  out, nullptr, HID_,  b2, x2);
}